// round 8
// baseline (speedup 1.0000x reference)
#include <cuda_runtime.h>
#include <math.h>

// Gaussian-mixture splat:
//   per plane n (48), per pixel c (H*W):
//     gx = (c / H) / (W-1), gy = (c % H) / (H-1)
//     for k in 0..3:
//       dx = gx - mu_x[k]; dy = gy - mu_y[k]
//       t0 = S00*dx + S10*dy; t1 = S11*dy      (Sigma lower-triangular, t = Sigma^T d)
//       e  = exp(-0.5*(t0^2 + t1^2))
//     y = clip( sum(e*w) / max(1e-7, sum(e)), 0, 1 )
//
// exp(-0.5*q) == exp2f(-(a*t0)^2 - (a*t1)^2) with a = sqrt(0.5*log2(e)),
// folded into S00,S10,S11 once per thread.
//
// params[n, 28]: mu_x=p[0:4], mu_y=p[4:8], w=p[8:12],
//                Sigma[k] = p[12+4k .. +3] row-major 2x2 -> S00, (S01 zeroed by tril), S10, S11

__device__ __forceinline__ int read_dim(const void* p) {
    // Scalar may be int32 or float32 bit pattern; disambiguate.
    int v = *(const int*)p;
    if (v >= 2 && v <= (1 << 20)) return v;
    float f = __int_as_float(v);
    if (f >= 2.0f && f <= 1048576.0f) return (int)(f + 0.5f);
    return 0;
}

__global__ void __launch_bounds__(256) gsplat_kernel(
    const void* __restrict__ hp,
    const void* __restrict__ wp,
    const float* __restrict__ params,
    float* __restrict__ out,
    int HW)
{
    const int n = blockIdx.y;

    __shared__ float sp[28];
    if (threadIdx.x < 28) sp[threadIdx.x] = params[n * 28 + threadIdx.x];
    __syncthreads();

    int H = read_dim(hp);
    int W = read_dim(wp);
    if (H <= 1 || W <= 1 || H * W != HW) {
        // fallback: square image
        int r = (int)(sqrtf((float)HW) + 0.5f);
        H = r; W = r;
    }
    const float inv_wm1 = 1.0f / (float)(W - 1);
    const float inv_hm1 = 1.0f / (float)(H - 1);

    const int idx = blockIdx.x * blockDim.x + threadIdx.x;
    const int c0 = idx * 4;
    if (c0 >= HW) return;

    const int i  = c0 / H;       // constant across the 4 pixels (H % 4 == 0)
    const int j0 = c0 - i * H;
    const float gx  = (float)i  * inv_wm1;
    const float gy0 = (float)j0 * inv_hm1;

    // a = sqrt(0.5 * log2(e)); folds the -0.5*log2e exp2 argument scale into Sigma
    const float A = 0.84932327f;

    float muy[4], wk[4], s10[4], s11[4], a0[4];
#pragma unroll
    for (int k = 0; k < 4; k++) {
        const float mux = sp[k];
        muy[k] = sp[4 + k];
        wk[k]  = sp[8 + k];
        const float s00 = A * sp[12 + 4 * k + 0];
        s10[k] = A * sp[12 + 4 * k + 2];
        s11[k] = A * sp[12 + 4 * k + 3];
        a0[k]  = s00 * (gx - mux);   // constant across the 4 pixels of this thread
    }

    float res[4];
#pragma unroll
    for (int t = 0; t < 4; t++) {
        const float gy = fmaf((float)t, inv_hm1, gy0);   // no per-pixel I2F
        float g = 0.0f, s = 0.0f;
#pragma unroll
        for (int k = 0; k < 4; k++) {
            const float dy = gy - muy[k];
            const float t0 = fmaf(s10[k], dy, a0[k]);
            const float t1 = s11[k] * dy;
            // q = -(t0^2) - (t1^2); negations fold into FFMA/FMUL operand modifiers
            const float q  = fmaf(t0, -t0, -(t1 * t1));
            const float e  = exp2f(q);          // exp(-0.5 * ||Sigma^T d||^2)
            g += e;
            s = fmaf(e, wk[k], s);
        }
        const float y = __fdividef(s, fmaxf(1e-7f, g));
        res[t] = __saturatef(y);
    }

    float* dst = out + (size_t)n * HW + c0;
    if (c0 + 4 <= HW) {
        float4 v = make_float4(res[0], res[1], res[2], res[3]);
        *reinterpret_cast<float4*>(dst) = v;
    } else {
        for (int t = 0; t < 4 && c0 + t < HW; t++) dst[t] = res[t];
    }
}

extern "C" void kernel_launch(void* const* d_in, const int* in_sizes, int n_in,
                              void* d_out, int out_size)
{
    const void*  hp     = d_in[0];
    const void*  wp     = d_in[1];
    const float* params = (const float*)d_in[2];
    float*       out    = (float*)d_out;

    const int N  = in_sizes[2] / 28;          // B*CH = 48
    const int HW = out_size / N;              // pixels per plane

    const int threads = 256;
    const int quads   = (HW + 3) / 4;
    dim3 grid((quads + threads - 1) / threads, N);
    gsplat_kernel<<<grid, threads>>>(hp, wp, params, out, HW);
}

// round 12
// speedup vs baseline: 1.2157x; 1.2157x over previous
#include <cuda_runtime.h>
#include <math.h>

// Gaussian-mixture splat:
//   per plane n (48), per pixel c (H*W):
//     gx = (c / H) / (W-1), gy = (c % H) / (H-1)
//     for k in 0..3:
//       t0 = S00*dx + S10*dy; t1 = S11*dy   (Sigma lower-triangular, t = Sigma^T d)
//       e  = exp(-0.5*(t0^2 + t1^2))
//     y = clip( sum(e*w) / max(1e-7, sum(e)), 0, 1 )
//
// exp(-0.5*q) == exp2f(-(a*t0)^2 - (a*t1)^2), a = sqrt(0.5*log2(e)) folded into Sigma.
// Issue-bound kernel (R8 ncu: issue=86%, prologue ~72% of slots) -> 16 px/thread,
// incremental t0/t1 updates along the column, fast reciprocals.

#define PX 16

__device__ __forceinline__ int read_dim(const void* p) {
    int v = *(const int*)p;
    if (v >= 2 && v <= (1 << 20)) return v;
    float f = __int_as_float(v);
    if (f >= 2.0f && f <= 1048576.0f) return (int)(f + 0.5f);
    return 0;
}

__global__ void __launch_bounds__(256) gsplat_kernel(
    const void* __restrict__ hp,
    const void* __restrict__ wp,
    const float* __restrict__ params,
    float* __restrict__ out,
    int HW)
{
    const int n = blockIdx.y;

    __shared__ float sp[28];
    if (threadIdx.x < 28) sp[threadIdx.x] = params[n * 28 + threadIdx.x];
    __syncthreads();

    int H = read_dim(hp);
    int W = read_dim(wp);
    if (H <= 1 || W <= 1 || H * W != HW) {
        int r = (int)(sqrtf((float)HW) + 0.5f);
        H = r; W = r;
    }
    const float inv_wm1 = __fdividef(1.0f, (float)(W - 1));
    const float inv_hm1 = __fdividef(1.0f, (float)(H - 1));

    const int idx = blockIdx.x * blockDim.x + threadIdx.x;
    const int c0 = idx * PX;
    if (c0 >= HW) return;

    const int i  = c0 / H;
    const int j0 = c0 - i * H;

    // a = sqrt(0.5 * log2(e)) : folds the exp->exp2 scale into Sigma
    const float A = 0.84932327f;

    float* dst = out + (size_t)n * HW + c0;

    if (j0 + PX <= H && c0 + PX <= HW) {
        // ---- fast path: PX pixels in one column, incremental updates ----
        const float gx  = (float)i  * inv_wm1;
        const float gy0 = (float)j0 * inv_hm1;

        float wk[4], t0[4], t1[4], d0[4], d1[4];
#pragma unroll
        for (int k = 0; k < 4; k++) {
            const float mux = sp[k];
            const float muy = sp[4 + k];
            wk[k] = sp[8 + k];
            const float s00 = A * sp[12 + 4 * k + 0];
            const float s10 = A * sp[12 + 4 * k + 2];
            const float s11 = A * sp[12 + 4 * k + 3];
            const float a0  = s00 * (gx - mux);
            const float dy0 = gy0 - muy;
            t0[k] = fmaf(s10, dy0, a0);
            t1[k] = s11 * dy0;
            d0[k] = s10 * inv_hm1;      // per-pixel increment along the column
            d1[k] = s11 * inv_hm1;
        }

        float res[4];
#pragma unroll
        for (int t = 0; t < PX; t++) {
            float g = 0.0f, s = 0.0f;
#pragma unroll
            for (int k = 0; k < 4; k++) {
                const float q = fmaf(t0[k], -t0[k], -(t1[k] * t1[k]));
                const float e = exp2f(q);
                g += e;
                s = fmaf(e, wk[k], s);
                t0[k] += d0[k];
                t1[k] += d1[k];
            }
            const float y = __fdividef(s, fmaxf(1e-7f, g));
            res[t & 3] = __saturatef(y);
            if ((t & 3) == 3) {
                *reinterpret_cast<float4*>(dst + (t - 3)) =
                    make_float4(res[0], res[1], res[2], res[3]);
            }
        }
    } else {
        // ---- generic fallback (column crossing / ragged tail) ----
        for (int t = 0; t < PX; t++) {
            const int c = c0 + t;
            if (c >= HW) break;
            const int ii = c / H;
            const int jj = c - ii * H;
            const float gx = (float)ii * inv_wm1;
            const float gy = (float)jj * inv_hm1;
            float g = 0.0f, s = 0.0f;
#pragma unroll
            for (int k = 0; k < 4; k++) {
                const float s00 = A * sp[12 + 4 * k + 0];
                const float s10 = A * sp[12 + 4 * k + 2];
                const float s11 = A * sp[12 + 4 * k + 3];
                const float dx = gx - sp[k];
                const float dy = gy - sp[4 + k];
                const float t0 = fmaf(s10, dy, s00 * dx);
                const float t1 = s11 * dy;
                const float q  = fmaf(t0, -t0, -(t1 * t1));
                const float e  = exp2f(q);
                g += e;
                s = fmaf(e, sp[8 + k], s);
            }
            dst[t] = __saturatef(__fdividef(s, fmaxf(1e-7f, g)));
        }
    }
}

extern "C" void kernel_launch(void* const* d_in, const int* in_sizes, int n_in,
                              void* d_out, int out_size)
{
    const void*  hp     = d_in[0];
    const void*  wp     = d_in[1];
    const float* params = (const float*)d_in[2];
    float*       out    = (float*)d_out;

    const int N  = in_sizes[2] / 28;   // B*CH = 48
    const int HW = out_size / N;       // pixels per plane

    const int threads = 256;
    const int chunks  = (HW + PX - 1) / PX;
    dim3 grid((chunks + threads - 1) / threads, N);
    gsplat_kernel<<<grid, threads>>>(hp, wp, params, out, HW);
}